// round 8
// baseline (speedup 1.0000x reference)
#include <cuda_runtime.h>
#include <math.h>

// B = H = IN = 256, c = 1. Dead code (Wh*/Uh*, r_point_h) skipped.

#define NB 256
#define MAXN 0.996f          // (1 - 4e-3)/sqrt(c)
#define EPSN 1e-15f
#define CLIPV 0.9999999f     // 1 - 1e-7 in f32

// ---------------- scratch ---------------------------------------------------
__device__ float g_w[4][NB * NB];     // w = sinh(mlr logits) per fc, [b][cl]
__device__ float g_scale[4][NB];      // sqrt(row-sumsq of w)+1
__device__ float g_nz[4][NB];         // ||z_cl||
__device__ float g_coef[4][NB];       // 2*||z_cl||/cosh(r_cl)^2
__device__ float g_y2[2][NB];         // ||x_b||^2 : [0]=hidden, [1]=hyp_x

// ---------------- fast math helpers -----------------------------------------
__device__ __forceinline__ float fsqrt_(float x) { float r; asm("sqrt.approx.f32 %0,%1;" : "=f"(r) : "f"(x)); return r; }
__device__ __forceinline__ float frcp_(float x)  { float r; asm("rcp.approx.f32 %0,%1;"  : "=f"(r) : "f"(x)); return r; }
__device__ __forceinline__ float ftanh_(float x) { float e = __expf(2.0f * x); return 1.0f - 2.0f * frcp_(e + 1.0f); }
__device__ __forceinline__ float fatanh_(float x){ return 0.5f * __logf((1.0f + x) * frcp_(1.0f - x)); }
__device__ __forceinline__ float fasinh_(float x){ float a = fabsf(x); float l = __logf(a + fsqrt_(fmaf(a, a, 1.0f))); return copysignf(l, x); }
__device__ __forceinline__ float fsinh_(float x) { float e = __expf(x); return 0.5f * (e - frcp_(e)); }
__device__ __forceinline__ float fsigm_(float x) { return frcp_(1.0f + __expf(-x)); }

__device__ __forceinline__ float wsum8(float v) {
    #pragma unroll
    for (int o = 16; o; o >>= 1) v += __shfl_xor_sync(0xffffffffu, v, o);
    return v;
}

// ---------------- K0: per-row stats (warp per row) ---------------------------
__global__ void k0_stats(const float* __restrict__ Wz_z, const float* __restrict__ Wz_r,
                         const float* __restrict__ Uz_z, const float* __restrict__ Uz_r,
                         const float* __restrict__ Wr_z, const float* __restrict__ Wr_r,
                         const float* __restrict__ Ur_z, const float* __restrict__ Ur_r,
                         const float* __restrict__ hidden, const float* __restrict__ hyp_x)
{
    const int gw = (blockIdx.x * blockDim.x + threadIdx.x) >> 5;
    const int lane = threadIdx.x & 31;
    const int m = gw >> 8, row = gw & 255;
    const float* p;
    if      (m == 0) p = Wz_z;
    else if (m == 1) p = Uz_z;
    else if (m == 2) p = Wr_z;
    else if (m == 3) p = Ur_z;
    else if (m == 4) p = hidden;
    else             p = hyp_x;

    const float4* p4 = reinterpret_cast<const float4*>(p + row * NB);
    float4 v0 = p4[lane], v1 = p4[lane + 32];
    float s = v0.x*v0.x + v0.y*v0.y + v0.z*v0.z + v0.w*v0.w
            + v1.x*v1.x + v1.y*v1.y + v1.z*v1.z + v1.w*v1.w;
    s = wsum8(s);
    if (lane == 0) {
        if (m < 4) {
            const float* R;
            if      (m == 0) R = Wz_r;
            else if (m == 1) R = Uz_r;
            else if (m == 2) R = Wr_r;
            else             R = Ur_r;
            float nz = sqrtf(s);
            g_nz[m][row] = nz;
            float ch = coshf(R[row]);
            g_coef[m][row] = 2.0f * nz / (ch * ch);
        } else {
            g_y2[m - 4][row] = s;
        }
    }
}

// ---------------- mlr/sinh epilogue ------------------------------------------
__device__ __forceinline__ float fc_elem(int fc, int cl, float rb, float y2b, float g)
{
    const float nz = g_nz[fc][cl];
    const float s  = g * frcp_(nz);
    float alpha = ftanh_(rb * nz);
    float aa = fabsf(alpha);
    if (aa > MAXN) alpha *= MAXN * frcp_(aa);
    const float x2 = alpha * alpha;
    const float xy = -alpha * s;
    const float A  = 1.0f + 2.0f * xy + y2b;
    const float Bc = 1.0f - x2;
    const float den = fmaxf(1.0f + 2.0f * xy + x2 * y2b, EPSN);
    const float inv = frcp_(den);
    float pa = (Bc * s - A * alpha) * inv;
    float p2 = (A * A * x2 - 2.0f * A * Bc * alpha * s + Bc * Bc * y2b) * (inv * inv);
    float pn = fmaxf(fsqrt_(fmaxf(p2, 0.0f)), EPSN);
    if (pn > MAXN) { float f = MAXN * frcp_(pn); pa *= f; p2 *= f * f; }
    const float lam = 2.0f * frcp_(1.0f - p2);
    return fsinh_(g_coef[fc][cl] * fasinh_(pa * lam));
}

// ---------------- K1: 4 GEMMs, 64x32 tile, 4x2 microtile, 256 threads --------
__global__ void __launch_bounds__(256) k1_gemm(
    const float* __restrict__ hidden, const float* __restrict__ hyp_x,
    const float* __restrict__ Wz_z, const float* __restrict__ Wz_r,
    const float* __restrict__ Uz_z, const float* __restrict__ Uz_r,
    const float* __restrict__ Wr_z, const float* __restrict__ Wr_r,
    const float* __restrict__ Ur_z, const float* __restrict__ Ur_r)
{
    const int fc = blockIdx.z;
    const float *X, *Z, *R;
    int ysel;
    if      (fc == 0) { X = hidden; Z = Wz_z; R = Wz_r; ysel = 0; }
    else if (fc == 1) { X = hyp_x;  Z = Uz_z; R = Uz_r; ysel = 1; }
    else if (fc == 2) { X = hidden; Z = Wr_z; R = Wr_r; ysel = 0; }
    else              { X = hyp_x;  Z = Ur_z; R = Ur_r; ysel = 1; }

    __shared__ float4 Xs[64][17];
    __shared__ float4 Zs[32][17];

    const int b0 = blockIdx.y * 64, c0 = blockIdx.x * 32;
    const int tid = threadIdx.x;
    const int tx = tid & 15, ty = tid >> 4;

    float a00=0.f,a01=0.f,a10=0.f,a11=0.f,a20=0.f,a21=0.f,a30=0.f,a31=0.f;

    for (int kc = 0; kc < 256; kc += 64) {
        #pragma unroll
        for (int i = tid; i < 1024; i += 256) {
            const int r = i >> 4, c = i & 15;
            Xs[r][c] = reinterpret_cast<const float4*>(X + (b0 + r) * 256 + kc)[c];
        }
        #pragma unroll
        for (int i = tid; i < 512; i += 256) {
            const int r = i >> 4, c = i & 15;
            Zs[r][c] = reinterpret_cast<const float4*>(Z + (c0 + r) * 256 + kc)[c];
        }
        __syncthreads();
        #pragma unroll
        for (int q = 0; q < 16; q++) {
            const float4 x0 = Xs[ty][q],      x1 = Xs[ty + 16][q];
            const float4 x2 = Xs[ty + 32][q], x3 = Xs[ty + 48][q];
            const float4 z0 = Zs[tx][q],      z1 = Zs[tx + 16][q];
            a00 = fmaf(x0.x, z0.x, a00); a00 = fmaf(x0.y, z0.y, a00);
            a00 = fmaf(x0.z, z0.z, a00); a00 = fmaf(x0.w, z0.w, a00);
            a01 = fmaf(x0.x, z1.x, a01); a01 = fmaf(x0.y, z1.y, a01);
            a01 = fmaf(x0.z, z1.z, a01); a01 = fmaf(x0.w, z1.w, a01);
            a10 = fmaf(x1.x, z0.x, a10); a10 = fmaf(x1.y, z0.y, a10);
            a10 = fmaf(x1.z, z0.z, a10); a10 = fmaf(x1.w, z0.w, a10);
            a11 = fmaf(x1.x, z1.x, a11); a11 = fmaf(x1.y, z1.y, a11);
            a11 = fmaf(x1.z, z1.z, a11); a11 = fmaf(x1.w, z1.w, a11);
            a20 = fmaf(x2.x, z0.x, a20); a20 = fmaf(x2.y, z0.y, a20);
            a20 = fmaf(x2.z, z0.z, a20); a20 = fmaf(x2.w, z0.w, a20);
            a21 = fmaf(x2.x, z1.x, a21); a21 = fmaf(x2.y, z1.y, a21);
            a21 = fmaf(x2.z, z1.z, a21); a21 = fmaf(x2.w, z1.w, a21);
            a30 = fmaf(x3.x, z0.x, a30); a30 = fmaf(x3.y, z0.y, a30);
            a30 = fmaf(x3.z, z0.z, a30); a30 = fmaf(x3.w, z0.w, a30);
            a31 = fmaf(x3.x, z1.x, a31); a31 = fmaf(x3.y, z1.y, a31);
            a31 = fmaf(x3.z, z1.z, a31); a31 = fmaf(x3.w, z1.w, a31);
        }
        __syncthreads();
    }

    const int cA = c0 + tx, cB = c0 + tx + 16;
    float accs[4][2] = {{a00,a01},{a10,a11},{a20,a21},{a30,a31}};
    #pragma unroll
    for (int i = 0; i < 4; i++) {
        const int m = b0 + ty + 16 * i;
        const float rb = R[m];
        const float y2 = g_y2[ysel][m];
        g_w[fc][m * 256 + cA] = fc_elem(fc, cA, rb, y2, accs[i][0]);
        g_w[fc][m * 256 + cB] = fc_elem(fc, cB, rb, y2, accs[i][1]);
    }
}

// ---------------- K1b: per-row scale (warp per row, float4 loads) ------------
__global__ void k1b_scale()
{
    const int gw = (blockIdx.x * blockDim.x + threadIdx.x) >> 5;
    const int lane = threadIdx.x & 31;
    const int fc = gw >> 8, row = gw & 255;
    const float4* p4 = reinterpret_cast<const float4*>(&g_w[fc][row * NB]);
    float4 v0 = p4[lane], v1 = p4[lane + 32];
    float s = v0.x*v0.x + v0.y*v0.y + v0.z*v0.z + v0.w*v0.w
            + v1.x*v1.x + v1.y*v1.y + v1.z*v1.z + v1.w*v1.w;
    s = wsum8(s);
    if (lane == 0) g_scale[fc][row] = sqrtf(s) + 1.0f;
}

// ---------------- madd scalar helper -----------------------------------------
struct MS { float A, B, inv, m, nc; };
__device__ __forceinline__ MS madds(float sxx, float syy, float sxy)
{
    MS r;
    r.A = 1.0f + 2.0f * sxy + syy;
    r.B = 1.0f - sxx;
    float den = fmaxf(1.0f + 2.0f * sxy + sxx * syy, EPSN);
    r.inv = frcp_(den);
    float n2 = (r.A * r.A * sxx + 2.0f * r.A * r.B * sxy + r.B * r.B * syy) * r.inv * r.inv;
    float n = fmaxf(fsqrt_(fmaxf(n2, 0.0f)), EPSN);
    r.m = (n > MAXN) ? MAXN * frcp_(n) : 1.0f;
    r.nc = fminf(n, MAXN);
    return r;
}

// ---------------- K2: 64 threads per row (2 warps, 4 elems/thread) -----------
// block = 256 threads = 4 rows; grid = 64. 3 reduction rounds, 1 barrier each.
__global__ void k2_final(
    const float* __restrict__ hidden, const float* __restrict__ bz,
    const float* __restrict__ br, const float* __restrict__ bh,
    float* __restrict__ out)
{
    // disjoint smem regions per round -> one barrier per round, no WAR hazards
    __shared__ float smr1[4][2][15];
    __shared__ float smr2[4][2][4];
    __shared__ float smr3[4][2][2];

    const int tid = threadIdx.x;
    const int grp = tid >> 6;          // row group 0..3
    const int lt  = tid & 63;          // lane within group
    const int gw  = (tid >> 5) & 1;    // warp within group
    const int b   = blockIdx.x * 4 + grp;

    float hid[4], bhv[4], bzv[4], brv[4], F0[4], G0[4], F1[4], G1[4];
    #pragma unroll
    for (int i = 0; i < 4; i++) {
        const int j = lt + 64 * i;
        hid[i] = hidden[b * NB + j];
        bhv[i] = bh[j]; bzv[i] = bz[j]; brv[i] = br[j];
        F0[i] = g_scale[0][j] * g_w[0][b * NB + j];
        G0[i] = g_scale[1][j] * g_w[1][b * NB + j];
        F1[i] = g_scale[2][j] * g_w[2][b * NB + j];
        G1[i] = g_scale[3][j] * g_w[3][b * NB + j];
    }

    // ---- round 1: 15 sums ----
    float v[15];
    #pragma unroll
    for (int k = 0; k < 15; k++) v[k] = 0.0f;
    #pragma unroll
    for (int i = 0; i < 4; i++) {
        v[0]  = fmaf(F0[i], F0[i], v[0]);  v[1]  = fmaf(G0[i], G0[i], v[1]);
        v[2]  = fmaf(F0[i], G0[i], v[2]);  v[3]  = fmaf(F0[i], bzv[i], v[3]);
        v[4]  = fmaf(G0[i], bzv[i], v[4]); v[5]  = fmaf(bzv[i], bzv[i], v[5]);
        v[6]  = fmaf(F1[i], F1[i], v[6]);  v[7]  = fmaf(G1[i], G1[i], v[7]);
        v[8]  = fmaf(F1[i], G1[i], v[8]);  v[9]  = fmaf(F1[i], brv[i], v[9]);
        v[10] = fmaf(G1[i], brv[i], v[10]);v[11] = fmaf(brv[i], brv[i], v[11]);
        v[12] = fmaf(hid[i], hid[i], v[12]);v[13] = fmaf(bhv[i], bhv[i], v[13]);
        v[14] = fmaf(hid[i], bhv[i], v[14]);
    }
    #pragma unroll
    for (int k = 0; k < 15; k++) {
        #pragma unroll
        for (int o = 16; o; o >>= 1) v[k] += __shfl_xor_sync(0xffffffffu, v[k], o);
    }
    if ((tid & 31) == 0) {
        #pragma unroll
        for (int k = 0; k < 15; k++) smr1[grp][gw][k] = v[k];
    }
    __syncthreads();
    #pragma unroll
    for (int k = 0; k < 15; k++) v[k] = smr1[grp][0][k] + smr1[grp][1][k];

    const float sFF0 = v[0], sGG0 = v[1], sFG0 = v[2], sFb0 = v[3], sGb0 = v[4], sbb0 = v[5];
    const float sFF1 = v[6], sGG1 = v[7], sFG1 = v[8], sFb1 = v[9], sGb1 = v[10], sbb1 = v[11];
    const float shh = v[12], sbhbh = v[13], shbh = v[14];

    // ---- z gate (closed form) ----
    MS z1 = madds(sFF0, sGG0, sFG0);
    float zcF = z1.m * z1.inv * z1.A, zcG = z1.m * z1.inv * z1.B;
    MS z2 = madds(z1.nc * z1.nc, sbb0, zcF * sFb0 + zcG * sGb0);
    float k2a = z2.m * z2.inv * z2.A, k2b = z2.m * z2.inv * z2.B;
    float facz = fatanh_(z2.nc) * frcp_(z2.nc);
    float zg[4];
    #pragma unroll
    for (int i = 0; i < 4; i++)
        zg[i] = fsigm_(facz * (k2a * (zcF * F0[i] + zcG * G0[i]) + k2b * bzv[i]));

    // ---- r gate ----
    MS r1 = madds(sFF1, sGG1, sFG1);
    float rcF = r1.m * r1.inv * r1.A, rcG = r1.m * r1.inv * r1.B;
    MS r2 = madds(r1.nc * r1.nc, sbb1, rcF * sFb1 + rcG * sGb1);
    float l2a = r2.m * r2.inv * r2.A, l2b = r2.m * r2.inv * r2.B;
    float facr = fatanh_(r2.nc) * frcp_(r2.nc);
    float rg[4];
    #pragma unroll
    for (int i = 0; i < 4; i++)
        rg[i] = fsigm_(facr * (l2a * (rcF * F1[i] + rcG * G1[i]) + l2b * brv[i]));

    // ---- round 2: 4 sums ----
    float v2[4] = {0.f, 0.f, 0.f, 0.f};
    #pragma unroll
    for (int i = 0; i < 4; i++) {
        v2[0] = fmaf(rg[i], rg[i], v2[0]);  v2[1] = fmaf(rg[i], bhv[i], v2[1]);
        v2[2] = fmaf(hid[i], rg[i], v2[2]); v2[3] = fmaf(zg[i], zg[i], v2[3]);
    }
    #pragma unroll
    for (int k = 0; k < 4; k++) {
        #pragma unroll
        for (int o = 16; o; o >>= 1) v2[k] += __shfl_xor_sync(0xffffffffu, v2[k], o);
    }
    if ((tid & 31) == 0) {
        #pragma unroll
        for (int k = 0; k < 4; k++) smr2[grp][gw][k] = v2[k];
    }
    __syncthreads();
    #pragma unroll
    for (int k = 0; k < 4; k++) v2[k] = smr2[grp][0][k] + smr2[grp][1][k];
    const float srr = v2[0], srbh = v2[1], shr = v2[2], szz = v2[3];

    // ---- h_tilde = madd(rg, bh); mh = madd(-hid, ht) ----
    MS h3 = madds(srr, sbhbh, srbh);
    float hA = h3.m * h3.inv * h3.A, hB = h3.m * h3.inv * h3.B;
    float sht_h = hA * shr + hB * shbh;
    MS h4 = madds(shh, h3.nc * h3.nc, -sht_h);
    float mA = -h4.m * h4.inv * h4.A;
    float mR =  h4.m * h4.inv * h4.B * hA;
    float mB =  h4.m * h4.inv * h4.B * hB;

    // ---- round 3: 2 sums ----
    float wx[4];
    float v3[2] = {0.f, 0.f};
    #pragma unroll
    for (int i = 0; i < 4; i++) {
        wx[i] = (mA * hid[i] + mR * rg[i] + mB * bhv[i]) * zg[i];
        v3[0] = fmaf(wx[i], wx[i], v3[0]);
        v3[1] = fmaf(hid[i], wx[i], v3[1]);
    }
    #pragma unroll
    for (int k = 0; k < 2; k++) {
        #pragma unroll
        for (int o = 16; o; o >>= 1) v3[k] += __shfl_xor_sync(0xffffffffu, v3[k], o);
    }
    if ((tid & 31) == 0) {
        #pragma unroll
        for (int k = 0; k < 2; k++) smr3[grp][gw][k] = v3[k];
    }
    __syncthreads();
    const float swx  = smr3[grp][0][0] + smr3[grp][1][0];
    const float shwx = smr3[grp][0][1] + smr3[grp][1][1];

    // ---- mobius pointwise mul + final add (closed form) ----
    float xn  = fmaxf(fsqrt_(szz), EPSN);
    float wxn = fmaxf(fsqrt_(swx), EPSN);
    float tt  = fatanh_(fminf(xn, CLIPV));
    float f   = ftanh_(wxn * frcp_(xn) * tt);
    float pn  = fmaxf(f, EPSN);
    float cf  = f * frcp_(wxn);
    if (pn > MAXN) cf *= MAXN * frcp_(pn);
    float pnc = fminf(pn, MAXN);

    MS o5 = madds(shh, pnc * pnc, cf * shwx);
    float oH = o5.m * o5.inv * o5.A, oP = o5.m * o5.inv * o5.B * cf;

    #pragma unroll
    for (int i = 0; i < 4; i++)
        out[b * NB + lt + 64 * i] = oH * hid[i] + oP * wx[i];
}

// ---------------- launch ------------------------------------------------------
extern "C" void kernel_launch(void* const* d_in, const int* in_sizes, int n_in,
                              void* d_out, int out_size)
{
    const float* hyp_x  = (const float*)d_in[0];
    const float* hidden = (const float*)d_in[1];
    const float* Wz_z   = (const float*)d_in[2];
    const float* Wz_r   = (const float*)d_in[3];
    const float* Uz_z   = (const float*)d_in[4];
    const float* Uz_r   = (const float*)d_in[5];
    const float* Wr_z   = (const float*)d_in[6];
    const float* Wr_r   = (const float*)d_in[7];
    const float* Ur_z   = (const float*)d_in[8];
    const float* Ur_r   = (const float*)d_in[9];
    const float* b_z    = (const float*)d_in[14];
    const float* b_r    = (const float*)d_in[15];
    const float* b_h    = (const float*)d_in[16];
    float* out = (float*)d_out;

    k0_stats<<<192, 256>>>(Wz_z, Wz_r, Uz_z, Uz_r, Wr_z, Wr_r, Ur_z, Ur_r, hidden, hyp_x);
    k1_gemm<<<dim3(8, 4, 4), 256>>>(hidden, hyp_x, Wz_z, Wz_r, Uz_z, Uz_r,
                                    Wr_z, Wr_r, Ur_z, Ur_r);
    k1b_scale<<<128, 256>>>();
    k2_final<<<64, 256>>>(hidden, b_z, b_r, b_h, out);
}

// round 9
// speedup vs baseline: 1.3902x; 1.3902x over previous
#include <cuda_runtime.h>
#include <math.h>

// B = H = IN = 256, c = 1. Dead code (Wh*/Uh*, r_point_h) skipped.

#define NB 256
#define MAXN 0.996f          // (1 - 4e-3)/sqrt(c)
#define EPSN 1e-15f
#define CLIPV 0.9999999f     // 1 - 1e-7 in f32

// ---------------- scratch ---------------------------------------------------
__device__ float g_w[4][NB * NB];     // w = sinh(mlr logits) per fc, [b][cl]
__device__ float g_part[4][NB][8];    // per-(row, n-tile) partial sumsq of w
__device__ float g_scale[4][NB];      // sqrt(row-sumsq of w)+1
__device__ float g_nz[4][NB];         // ||z_cl||
__device__ float g_coef[4][NB];       // 2*||z_cl||/cosh(r_cl)^2
__device__ float g_y2[2][NB];         // ||x_b||^2 : [0]=hidden, [1]=hyp_x

// ---------------- fast math helpers -----------------------------------------
__device__ __forceinline__ float fsqrt_(float x) { float r; asm("sqrt.approx.f32 %0,%1;" : "=f"(r) : "f"(x)); return r; }
__device__ __forceinline__ float frcp_(float x)  { float r; asm("rcp.approx.f32 %0,%1;"  : "=f"(r) : "f"(x)); return r; }
__device__ __forceinline__ float ftanh_(float x) { float e = __expf(2.0f * x); return 1.0f - 2.0f * frcp_(e + 1.0f); }
__device__ __forceinline__ float fatanh_(float x){ return 0.5f * __logf((1.0f + x) * frcp_(1.0f - x)); }
__device__ __forceinline__ float fasinh_(float x){ float a = fabsf(x); float l = __logf(a + fsqrt_(fmaf(a, a, 1.0f))); return copysignf(l, x); }
__device__ __forceinline__ float fsinh_(float x) { float e = __expf(x); return 0.5f * (e - frcp_(e)); }
__device__ __forceinline__ float fsigm_(float x) { return frcp_(1.0f + __expf(-x)); }

__device__ __forceinline__ float wsum8(float v) {
    #pragma unroll
    for (int o = 16; o; o >>= 1) v += __shfl_xor_sync(0xffffffffu, v, o);
    return v;
}

// ---------------- K0: per-row stats (warp per row) ---------------------------
__global__ void k0_stats(const float* __restrict__ Wz_z, const float* __restrict__ Wz_r,
                         const float* __restrict__ Uz_z, const float* __restrict__ Uz_r,
                         const float* __restrict__ Wr_z, const float* __restrict__ Wr_r,
                         const float* __restrict__ Ur_z, const float* __restrict__ Ur_r,
                         const float* __restrict__ hidden, const float* __restrict__ hyp_x)
{
    const int gw = (blockIdx.x * blockDim.x + threadIdx.x) >> 5;
    const int lane = threadIdx.x & 31;
    const int m = gw >> 8, row = gw & 255;
    const float* p;
    if      (m == 0) p = Wz_z;
    else if (m == 1) p = Uz_z;
    else if (m == 2) p = Wr_z;
    else if (m == 3) p = Ur_z;
    else if (m == 4) p = hidden;
    else             p = hyp_x;

    const float4* p4 = reinterpret_cast<const float4*>(p + row * NB);
    float4 v0 = p4[lane], v1 = p4[lane + 32];
    float s = v0.x*v0.x + v0.y*v0.y + v0.z*v0.z + v0.w*v0.w
            + v1.x*v1.x + v1.y*v1.y + v1.z*v1.z + v1.w*v1.w;
    s = wsum8(s);
    if (lane == 0) {
        if (m < 4) {
            const float* R;
            if      (m == 0) R = Wz_r;
            else if (m == 1) R = Uz_r;
            else if (m == 2) R = Wr_r;
            else             R = Ur_r;
            float nz = sqrtf(s);
            g_nz[m][row] = nz;
            float ch = coshf(R[row]);
            g_coef[m][row] = 2.0f * nz / (ch * ch);
        } else {
            g_y2[m - 4][row] = s;
        }
    }
}

// ---------------- mlr/sinh epilogue ------------------------------------------
__device__ __forceinline__ float fc_elem(int fc, int cl, float rb, float y2b, float g)
{
    const float nz = g_nz[fc][cl];
    const float s  = g * frcp_(nz);
    float alpha = ftanh_(rb * nz);
    float aa = fabsf(alpha);
    if (aa > MAXN) alpha *= MAXN * frcp_(aa);
    const float x2 = alpha * alpha;
    const float xy = -alpha * s;
    const float A  = 1.0f + 2.0f * xy + y2b;
    const float Bc = 1.0f - x2;
    const float den = fmaxf(1.0f + 2.0f * xy + x2 * y2b, EPSN);
    const float inv = frcp_(den);
    float pa = (Bc * s - A * alpha) * inv;
    float p2 = (A * A * x2 - 2.0f * A * Bc * alpha * s + Bc * Bc * y2b) * (inv * inv);
    float pn = fmaxf(fsqrt_(fmaxf(p2, 0.0f)), EPSN);
    if (pn > MAXN) { float f = MAXN * frcp_(pn); pa *= f; p2 *= f * f; }
    const float lam = 2.0f * frcp_(1.0f - p2);
    return fsinh_(g_coef[fc][cl] * fasinh_(pa * lam));
}

// ---------------- K1: 4 GEMMs, 64x32 tile, 4x2 microtile, 256 threads --------
__global__ void __launch_bounds__(256) k1_gemm(
    const float* __restrict__ hidden, const float* __restrict__ hyp_x,
    const float* __restrict__ Wz_z, const float* __restrict__ Wz_r,
    const float* __restrict__ Uz_z, const float* __restrict__ Uz_r,
    const float* __restrict__ Wr_z, const float* __restrict__ Wr_r,
    const float* __restrict__ Ur_z, const float* __restrict__ Ur_r)
{
    const int fc = blockIdx.z;
    const float *X, *Z, *R;
    int ysel;
    if      (fc == 0) { X = hidden; Z = Wz_z; R = Wz_r; ysel = 0; }
    else if (fc == 1) { X = hyp_x;  Z = Uz_z; R = Uz_r; ysel = 1; }
    else if (fc == 2) { X = hidden; Z = Wr_z; R = Wr_r; ysel = 0; }
    else              { X = hyp_x;  Z = Ur_z; R = Ur_r; ysel = 1; }

    __shared__ float4 Xs[64][17];
    __shared__ float4 Zs[32][17];

    const int b0 = blockIdx.y * 64, c0 = blockIdx.x * 32;
    const int tid = threadIdx.x;
    const int tx = tid & 15, ty = tid >> 4;

    float a00=0.f,a01=0.f,a10=0.f,a11=0.f,a20=0.f,a21=0.f,a30=0.f,a31=0.f;

    for (int kc = 0; kc < 256; kc += 64) {
        #pragma unroll
        for (int i = tid; i < 1024; i += 256) {
            const int r = i >> 4, c = i & 15;
            Xs[r][c] = reinterpret_cast<const float4*>(X + (b0 + r) * 256 + kc)[c];
        }
        #pragma unroll
        for (int i = tid; i < 512; i += 256) {
            const int r = i >> 4, c = i & 15;
            Zs[r][c] = reinterpret_cast<const float4*>(Z + (c0 + r) * 256 + kc)[c];
        }
        __syncthreads();
        #pragma unroll
        for (int q = 0; q < 16; q++) {
            const float4 x0 = Xs[ty][q],      x1 = Xs[ty + 16][q];
            const float4 x2 = Xs[ty + 32][q], x3 = Xs[ty + 48][q];
            const float4 z0 = Zs[tx][q],      z1 = Zs[tx + 16][q];
            a00 = fmaf(x0.x, z0.x, a00); a00 = fmaf(x0.y, z0.y, a00);
            a00 = fmaf(x0.z, z0.z, a00); a00 = fmaf(x0.w, z0.w, a00);
            a01 = fmaf(x0.x, z1.x, a01); a01 = fmaf(x0.y, z1.y, a01);
            a01 = fmaf(x0.z, z1.z, a01); a01 = fmaf(x0.w, z1.w, a01);
            a10 = fmaf(x1.x, z0.x, a10); a10 = fmaf(x1.y, z0.y, a10);
            a10 = fmaf(x1.z, z0.z, a10); a10 = fmaf(x1.w, z0.w, a10);
            a11 = fmaf(x1.x, z1.x, a11); a11 = fmaf(x1.y, z1.y, a11);
            a11 = fmaf(x1.z, z1.z, a11); a11 = fmaf(x1.w, z1.w, a11);
            a20 = fmaf(x2.x, z0.x, a20); a20 = fmaf(x2.y, z0.y, a20);
            a20 = fmaf(x2.z, z0.z, a20); a20 = fmaf(x2.w, z0.w, a20);
            a21 = fmaf(x2.x, z1.x, a21); a21 = fmaf(x2.y, z1.y, a21);
            a21 = fmaf(x2.z, z1.z, a21); a21 = fmaf(x2.w, z1.w, a21);
            a30 = fmaf(x3.x, z0.x, a30); a30 = fmaf(x3.y, z0.y, a30);
            a30 = fmaf(x3.z, z0.z, a30); a30 = fmaf(x3.w, z0.w, a30);
            a31 = fmaf(x3.x, z1.x, a31); a31 = fmaf(x3.y, z1.y, a31);
            a31 = fmaf(x3.z, z1.z, a31); a31 = fmaf(x3.w, z1.w, a31);
        }
        __syncthreads();
    }

    const int cA = c0 + tx, cB = c0 + tx + 16;
    float accs[4][2] = {{a00,a01},{a10,a11},{a20,a21},{a30,a31}};
    float psum[4];
    #pragma unroll
    for (int i = 0; i < 4; i++) {
        const int m = b0 + ty + 16 * i;
        const float rb = R[m];
        const float y2 = g_y2[ysel][m];
        float wA = fc_elem(fc, cA, rb, y2, accs[i][0]);
        float wB = fc_elem(fc, cB, rb, y2, accs[i][1]);
        g_w[fc][m * 256 + cA] = wA;
        g_w[fc][m * 256 + cB] = wB;
        psum[i] = fmaf(wA, wA, wB * wB);
    }
    // reduce partial sumsq across the 16 tx-lanes sharing each m (half-warp)
    #pragma unroll
    for (int o = 8; o; o >>= 1) {
        #pragma unroll
        for (int i = 0; i < 4; i++) psum[i] += __shfl_xor_sync(0xffffffffu, psum[i], o);
    }
    if (tx == 0) {
        #pragma unroll
        for (int i = 0; i < 4; i++)
            g_part[fc][b0 + ty + 16 * i][blockIdx.x] = psum[i];
    }
}

// ---------------- K1b: sum 8 partials per row (tiny) -------------------------
__global__ void k1b_scale()
{
    const int idx = blockIdx.x * 256 + threadIdx.x;   // 0..1023 = fc*256+row
    const int fc = idx >> 8, row = idx & 255;
    const float4* p4 = reinterpret_cast<const float4*>(g_part[fc][row]);
    float4 v0 = p4[0], v1 = p4[1];
    float s = v0.x + v0.y + v0.z + v0.w + v1.x + v1.y + v1.z + v1.w;
    g_scale[fc][row] = sqrtf(s) + 1.0f;
}

// ---------------- batched per-half block reduction (256-thread halves) -------
template<int K>
__device__ __forceinline__ void bred2(float* v, float* sm, int ltid)
{
    const int lane = ltid & 31, wid = ltid >> 5;
    __syncthreads();
    #pragma unroll
    for (int k = 0; k < K; k++) {
        float x = v[k];
        #pragma unroll
        for (int o = 16; o; o >>= 1) x += __shfl_xor_sync(0xffffffffu, x, o);
        if (lane == 0) sm[k * 8 + wid] = x;
    }
    __syncthreads();
    if (ltid < K) {
        float s = sm[ltid * 8];
        #pragma unroll
        for (int w = 1; w < 8; w++) s += sm[ltid * 8 + w];
        sm[ltid * 8] = s;
    }
    __syncthreads();
    #pragma unroll
    for (int k = 0; k < K; k++) v[k] = sm[k * 8];
}

// ---------------- madd scalar helper -----------------------------------------
struct MS { float A, B, inv, m, nc; };
__device__ __forceinline__ MS madds(float sxx, float syy, float sxy)
{
    MS r;
    r.A = 1.0f + 2.0f * sxy + syy;
    r.B = 1.0f - sxx;
    float den = fmaxf(1.0f + 2.0f * sxy + sxx * syy, EPSN);
    r.inv = frcp_(den);
    float n2 = (r.A * r.A * sxx + 2.0f * r.A * r.B * sxy + r.B * r.B * syy) * r.inv * r.inv;
    float n = fmaxf(fsqrt_(fmaxf(n2, 0.0f)), EPSN);
    r.m = (n > MAXN) ? MAXN * frcp_(n) : 1.0f;
    r.nc = fminf(n, MAXN);
    return r;
}

// ---------------- K2: 2 rows per 512-thread block (R7 best) ------------------
__global__ void __launch_bounds__(512) k2_final(
    const float* __restrict__ hidden, const float* __restrict__ bz,
    const float* __restrict__ br, const float* __restrict__ bh,
    float* __restrict__ out)
{
    __shared__ float smbuf[2][15 * 8];
    const int half = threadIdx.x >> 8;
    const int ltid = threadIdx.x & 255;
    const int b = blockIdx.x * 2 + half;
    const int j = ltid;
    float* sm = smbuf[half];

    const float hid = hidden[b * NB + j];
    const float bhv = bh[j], bzv = bz[j], brv = br[j];
    const float F0 = g_scale[0][j] * g_w[0][b * NB + j];
    const float G0 = g_scale[1][j] * g_w[1][b * NB + j];
    const float F1 = g_scale[2][j] * g_w[2][b * NB + j];
    const float G1 = g_scale[3][j] * g_w[3][b * NB + j];

    // ---- round 1: 15 sums ----
    float v[15];
    v[0] = F0 * F0;  v[1] = G0 * G0;  v[2] = F0 * G0;
    v[3] = F0 * bzv; v[4] = G0 * bzv; v[5] = bzv * bzv;
    v[6] = F1 * F1;  v[7] = G1 * G1;  v[8] = F1 * G1;
    v[9] = F1 * brv; v[10] = G1 * brv; v[11] = brv * brv;
    v[12] = hid * hid; v[13] = bhv * bhv; v[14] = hid * bhv;
    bred2<15>(v, sm, ltid);
    const float sFF0 = v[0], sGG0 = v[1], sFG0 = v[2], sFb0 = v[3], sGb0 = v[4], sbb0 = v[5];
    const float sFF1 = v[6], sGG1 = v[7], sFG1 = v[8], sFb1 = v[9], sGb1 = v[10], sbb1 = v[11];
    const float shh = v[12], sbhbh = v[13], shbh = v[14];

    // ---- z gate ----
    MS z1 = madds(sFF0, sGG0, sFG0);
    float zcF = z1.m * z1.inv * z1.A, zcG = z1.m * z1.inv * z1.B;
    MS z2 = madds(z1.nc * z1.nc, sbb0, zcF * sFb0 + zcG * sGb0);
    float k2a = z2.m * z2.inv * z2.A, k2b = z2.m * z2.inv * z2.B;
    float facz = fatanh_(z2.nc) * frcp_(z2.nc);
    const float zg = fsigm_(facz * (k2a * (zcF * F0 + zcG * G0) + k2b * bzv));

    // ---- r gate ----
    MS r1 = madds(sFF1, sGG1, sFG1);
    float rcF = r1.m * r1.inv * r1.A, rcG = r1.m * r1.inv * r1.B;
    MS r2 = madds(r1.nc * r1.nc, sbb1, rcF * sFb1 + rcG * sGb1);
    float l2a = r2.m * r2.inv * r2.A, l2b = r2.m * r2.inv * r2.B;
    float facr = fatanh_(r2.nc) * frcp_(r2.nc);
    const float rg = fsigm_(facr * (l2a * (rcF * F1 + rcG * G1) + l2b * brv));

    // ---- round 2: 4 sums ----
    float v2[4];
    v2[0] = rg * rg; v2[1] = rg * bhv; v2[2] = hid * rg; v2[3] = zg * zg;
    bred2<4>(v2, sm, ltid);
    const float srr = v2[0], srbh = v2[1], shr = v2[2], szz = v2[3];

    // ---- h_tilde = madd(rg, bh); mh = madd(-hid, ht) ----
    MS h3 = madds(srr, sbhbh, srbh);
    float hA = h3.m * h3.inv * h3.A, hB = h3.m * h3.inv * h3.B;
    float sht_h = hA * shr + hB * shbh;
    MS h4 = madds(shh, h3.nc * h3.nc, -sht_h);
    float mA = -h4.m * h4.inv * h4.A;
    float mR =  h4.m * h4.inv * h4.B * hA;
    float mB =  h4.m * h4.inv * h4.B * hB;

    // ---- round 3: 2 sums ----
    const float wx = (mA * hid + mR * rg + mB * bhv) * zg;
    float v3[2];
    v3[0] = wx * wx; v3[1] = hid * wx;
    bred2<2>(v3, sm, ltid);
    const float swx = v3[0], shwx = v3[1];

    // ---- mobius pointwise mul + final add ----
    float xn  = fmaxf(fsqrt_(szz), EPSN);
    float wxn = fmaxf(fsqrt_(swx), EPSN);
    float tt  = fatanh_(fminf(xn, CLIPV));
    float f   = ftanh_(wxn * frcp_(xn) * tt);
    float pn  = fmaxf(f, EPSN);
    float cf  = f * frcp_(wxn);
    if (pn > MAXN) cf *= MAXN * frcp_(pn);
    float pnc = fminf(pn, MAXN);

    MS o5 = madds(shh, pnc * pnc, cf * shwx);
    float oH = o5.m * o5.inv * o5.A, oP = o5.m * o5.inv * o5.B * cf;

    out[b * NB + j] = oH * hid + oP * wx;
}

// ---------------- launch ------------------------------------------------------
extern "C" void kernel_launch(void* const* d_in, const int* in_sizes, int n_in,
                              void* d_out, int out_size)
{
    const float* hyp_x  = (const float*)d_in[0];
    const float* hidden = (const float*)d_in[1];
    const float* Wz_z   = (const float*)d_in[2];
    const float* Wz_r   = (const float*)d_in[3];
    const float* Uz_z   = (const float*)d_in[4];
    const float* Uz_r   = (const float*)d_in[5];
    const float* Wr_z   = (const float*)d_in[6];
    const float* Wr_r   = (const float*)d_in[7];
    const float* Ur_z   = (const float*)d_in[8];
    const float* Ur_r   = (const float*)d_in[9];
    const float* b_z    = (const float*)d_in[14];
    const float* b_r    = (const float*)d_in[15];
    const float* b_h    = (const float*)d_in[16];
    float* out = (float*)d_out;

    k0_stats<<<192, 256>>>(Wz_z, Wz_r, Uz_z, Uz_r, Wr_z, Wr_r, Ur_z, Ur_r, hidden, hyp_x);
    k1_gemm<<<dim3(8, 4, 4), 256>>>(hidden, hyp_x, Wz_z, Wz_r, Uz_z, Uz_r,
                                    Wr_z, Wr_r, Ur_z, Ur_r);
    k1b_scale<<<4, 256>>>();
    k2_final<<<128, 512>>>(hidden, b_z, b_r, b_h, out);
}

// round 10
// speedup vs baseline: 1.5431x; 1.1100x over previous
#include <cuda_runtime.h>
#include <math.h>

// B = H = IN = 256, c = 1. Dead code (Wh*/Uh*, r_point_h) skipped.
// Single fused kernel: GEMM+epilogue phase, grid barrier, gate/cell phase.

#define NB 256
#define MAXN 0.996f          // (1 - 4e-3)/sqrt(c)
#define EPSN 1e-15f
#define CLIPV 0.9999999f     // 1 - 1e-7 in f32
#define NBLOCKS 128u

// ---------------- scratch ---------------------------------------------------
__device__ float g_w[4][NB * NB];     // w = sinh(mlr logits) per fc, [b][cl]
__device__ float g_part[4][NB][8];    // per-(row, n-tile) partial sumsq of w
__device__ unsigned g_cnt;            // zero-initialized
__device__ unsigned g_gen;            // zero-initialized

// ---------------- fast math helpers -----------------------------------------
__device__ __forceinline__ float fsqrt_(float x) { float r; asm("sqrt.approx.f32 %0,%1;" : "=f"(r) : "f"(x)); return r; }
__device__ __forceinline__ float frcp_(float x)  { float r; asm("rcp.approx.f32 %0,%1;"  : "=f"(r) : "f"(x)); return r; }
__device__ __forceinline__ float ftanh_(float x) { float e = __expf(2.0f * x); return 1.0f - 2.0f * frcp_(e + 1.0f); }
__device__ __forceinline__ float fatanh_(float x){ return 0.5f * __logf((1.0f + x) * frcp_(1.0f - x)); }
__device__ __forceinline__ float fasinh_(float x){ float a = fabsf(x); float l = __logf(a + fsqrt_(fmaf(a, a, 1.0f))); return copysignf(l, x); }
__device__ __forceinline__ float fsinh_(float x) { float e = __expf(x); return 0.5f * (e - frcp_(e)); }
__device__ __forceinline__ float fsigm_(float x) { return frcp_(1.0f + __expf(-x)); }

// ---------------- grid barrier (all 128 CTAs resident) -----------------------
__device__ __forceinline__ void grid_bar()
{
    __threadfence();
    __syncthreads();
    if (threadIdx.x == 0) {
        unsigned gen = *(volatile unsigned*)&g_gen;
        unsigned t = atomicAdd(&g_cnt, 1u);
        if (t == NBLOCKS - 1u) {
            *(volatile unsigned*)&g_cnt = 0u;
            __threadfence();
            *(volatile unsigned*)&g_gen = gen + 1u;
        } else {
            while (*(volatile unsigned*)&g_gen == gen) { }
        }
        __threadfence();
    }
    __syncthreads();
}

// ---------------- mlr/sinh epilogue ------------------------------------------
__device__ __forceinline__ float fc_elem(float nz, float inz, float coef,
                                         float rb, float y2b, float g)
{
    const float s  = g * inz;
    float alpha = ftanh_(rb * nz);
    float aa = fabsf(alpha);
    if (aa > MAXN) alpha *= MAXN * frcp_(aa);
    const float x2 = alpha * alpha;
    const float xy = -alpha * s;
    const float A  = 1.0f + 2.0f * xy + y2b;
    const float Bc = 1.0f - x2;
    const float den = fmaxf(1.0f + 2.0f * xy + x2 * y2b, EPSN);
    const float inv = frcp_(den);
    float pa = (Bc * s - A * alpha) * inv;
    float p2 = (A * A * x2 - 2.0f * A * Bc * alpha * s + Bc * Bc * y2b) * (inv * inv);
    float pn = fmaxf(fsqrt_(fmaxf(p2, 0.0f)), EPSN);
    if (pn > MAXN) { float f = MAXN * frcp_(pn); pa *= f; p2 *= f * f; }
    const float lam = 2.0f * frcp_(1.0f - p2);
    return fsinh_(coef * fasinh_(pa * lam));
}

// ---------------- madd scalar helper -----------------------------------------
struct MS { float A, B, inv, m, nc; };
__device__ __forceinline__ MS madds(float sxx, float syy, float sxy)
{
    MS r;
    r.A = 1.0f + 2.0f * sxy + syy;
    r.B = 1.0f - sxx;
    float den = fmaxf(1.0f + 2.0f * sxy + sxx * syy, EPSN);
    r.inv = frcp_(den);
    float n2 = (r.A * r.A * sxx + 2.0f * r.A * r.B * sxy + r.B * r.B * syy) * r.inv * r.inv;
    float n = fmaxf(fsqrt_(fmaxf(n2, 0.0f)), EPSN);
    r.m = (n > MAXN) ? MAXN * frcp_(n) : 1.0f;
    r.nc = fminf(n, MAXN);
    return r;
}

// ---------------- fused kernel ------------------------------------------------
__global__ void __launch_bounds__(256) fused_cell(
    const float* __restrict__ hidden, const float* __restrict__ hyp_x,
    const float* __restrict__ Wz_z, const float* __restrict__ Wz_r,
    const float* __restrict__ Uz_z, const float* __restrict__ Uz_r,
    const float* __restrict__ Wr_z, const float* __restrict__ Wr_r,
    const float* __restrict__ Ur_z, const float* __restrict__ Ur_r,
    const float* __restrict__ bz, const float* __restrict__ br,
    const float* __restrict__ bh, float* __restrict__ out)
{
    __shared__ float4 Xs[64][17];
    __shared__ float4 Zs[32][17];
    __shared__ float sX[64], sZ[32];
    __shared__ float s_scale[4][NB];
    __shared__ float smr1[2][4][15];
    __shared__ float smr2[2][4][4];
    __shared__ float smr3[2][4][2];

    const int tid = threadIdx.x;
    const int bid = blockIdx.x;

    // ================= PHASE 1: GEMM + mlr epilogue =================
    {
        const int nx = bid & 7, my = (bid >> 3) & 3, fc = bid >> 5;
        const float *X, *Z, *R;
        if      (fc == 0) { X = hidden; Z = Wz_z; R = Wz_r; }
        else if (fc == 1) { X = hyp_x;  Z = Uz_z; R = Uz_r; }
        else if (fc == 2) { X = hidden; Z = Wr_z; R = Wr_r; }
        else              { X = hyp_x;  Z = Ur_z; R = Ur_r; }

        const int b0 = my * 64, c0 = nx * 32;
        const int tx = tid & 15, ty = tid >> 4;

        float a00=0.f,a01=0.f,a10=0.f,a11=0.f,a20=0.f,a21=0.f,a30=0.f,a31=0.f;
        float xss[4] = {0.f,0.f,0.f,0.f};
        float zss[2] = {0.f,0.f};

        for (int kc = 0; kc < 256; kc += 64) {
            #pragma unroll
            for (int p = 0; p < 4; p++) {
                float4 v = reinterpret_cast<const float4*>(X + (b0 + ty + 16 * p) * 256 + kc)[tx];
                Xs[ty + 16 * p][tx] = v;
                xss[p] = fmaf(v.x, v.x, fmaf(v.y, v.y, fmaf(v.z, v.z, fmaf(v.w, v.w, xss[p]))));
            }
            #pragma unroll
            for (int p = 0; p < 2; p++) {
                float4 v = reinterpret_cast<const float4*>(Z + (c0 + ty + 16 * p) * 256 + kc)[tx];
                Zs[ty + 16 * p][tx] = v;
                zss[p] = fmaf(v.x, v.x, fmaf(v.y, v.y, fmaf(v.z, v.z, fmaf(v.w, v.w, zss[p]))));
            }
            __syncthreads();
            #pragma unroll
            for (int q = 0; q < 16; q++) {
                const float4 x0 = Xs[ty][q],      x1 = Xs[ty + 16][q];
                const float4 x2 = Xs[ty + 32][q], x3 = Xs[ty + 48][q];
                const float4 z0 = Zs[tx][q],      z1 = Zs[tx + 16][q];
                a00 = fmaf(x0.x, z0.x, a00); a00 = fmaf(x0.y, z0.y, a00);
                a00 = fmaf(x0.z, z0.z, a00); a00 = fmaf(x0.w, z0.w, a00);
                a01 = fmaf(x0.x, z1.x, a01); a01 = fmaf(x0.y, z1.y, a01);
                a01 = fmaf(x0.z, z1.z, a01); a01 = fmaf(x0.w, z1.w, a01);
                a10 = fmaf(x1.x, z0.x, a10); a10 = fmaf(x1.y, z0.y, a10);
                a10 = fmaf(x1.z, z0.z, a10); a10 = fmaf(x1.w, z0.w, a10);
                a11 = fmaf(x1.x, z1.x, a11); a11 = fmaf(x1.y, z1.y, a11);
                a11 = fmaf(x1.z, z1.z, a11); a11 = fmaf(x1.w, z1.w, a11);
                a20 = fmaf(x2.x, z0.x, a20); a20 = fmaf(x2.y, z0.y, a20);
                a20 = fmaf(x2.z, z0.z, a20); a20 = fmaf(x2.w, z0.w, a20);
                a21 = fmaf(x2.x, z1.x, a21); a21 = fmaf(x2.y, z1.y, a21);
                a21 = fmaf(x2.z, z1.z, a21); a21 = fmaf(x2.w, z1.w, a21);
                a30 = fmaf(x3.x, z0.x, a30); a30 = fmaf(x3.y, z0.y, a30);
                a30 = fmaf(x3.z, z0.z, a30); a30 = fmaf(x3.w, z0.w, a30);
                a31 = fmaf(x3.x, z1.x, a31); a31 = fmaf(x3.y, z1.y, a31);
                a31 = fmaf(x3.z, z1.z, a31); a31 = fmaf(x3.w, z1.w, a31);
            }
            __syncthreads();
        }

        // reduce row sumsq across the 16 tx lanes (xor < 16 stays in group)
        #pragma unroll
        for (int o = 8; o; o >>= 1) {
            #pragma unroll
            for (int p = 0; p < 4; p++) xss[p] += __shfl_xor_sync(0xffffffffu, xss[p], o);
            #pragma unroll
            for (int p = 0; p < 2; p++) zss[p] += __shfl_xor_sync(0xffffffffu, zss[p], o);
        }
        if (tx == 0) {
            #pragma unroll
            for (int p = 0; p < 4; p++) sX[ty + 16 * p] = xss[p];
            sZ[ty] = zss[0]; sZ[ty + 16] = zss[1];
        }
        __syncthreads();

        const int cA = c0 + tx, cB = c0 + tx + 16;
        const float nzA = sqrtf(sZ[tx]),      nzB = sqrtf(sZ[tx + 16]);
        const float izA = frcp_(nzA),          izB = frcp_(nzB);
        float eA = __expf(R[cA]); float chA = 0.5f * (eA + frcp_(eA));
        float eB = __expf(R[cB]); float chB = 0.5f * (eB + frcp_(eB));
        const float cfA = 2.0f * nzA * frcp_(chA * chA);
        const float cfB = 2.0f * nzB * frcp_(chB * chB);

        float accs[4][2] = {{a00,a01},{a10,a11},{a20,a21},{a30,a31}};
        float psum[4];
        #pragma unroll
        for (int i = 0; i < 4; i++) {
            const int m = b0 + ty + 16 * i;
            const float rb = R[m];
            const float y2 = sX[ty + 16 * i];
            float wA = fc_elem(nzA, izA, cfA, rb, y2, accs[i][0]);
            float wB = fc_elem(nzB, izB, cfB, rb, y2, accs[i][1]);
            g_w[fc][m * 256 + cA] = wA;
            g_w[fc][m * 256 + cB] = wB;
            psum[i] = fmaf(wA, wA, wB * wB);
        }
        #pragma unroll
        for (int o = 8; o; o >>= 1) {
            #pragma unroll
            for (int i = 0; i < 4; i++) psum[i] += __shfl_xor_sync(0xffffffffu, psum[i], o);
        }
        if (tx == 0) {
            #pragma unroll
            for (int i = 0; i < 4; i++)
                g_part[fc][b0 + ty + 16 * i][nx] = psum[i];
        }
    }

    // ================= GRID BARRIER =================
    grid_bar();

    // ================= PHASE 2: scales + gates + cell update =================
    // scales: thread tid computes s_scale[q][tid] for q = 0..3
    #pragma unroll
    for (int q = 0; q < 4; q++) {
        const float4* p4 = reinterpret_cast<const float4*>(g_part[q][tid]);
        float4 u0 = p4[0], u1 = p4[1];
        float s = u0.x + u0.y + u0.z + u0.w + u1.x + u1.y + u1.z + u1.w;
        s_scale[q][tid] = sqrtf(s) + 1.0f;
    }
    __syncthreads();

    // two 128-thread halves, one batch row each; 2 elems/thread
    const int half = tid >> 7;
    const int lt   = tid & 127;
    const int wih  = (tid >> 5) & 3;       // warp within half
    const int lane = tid & 31;
    const int b    = bid * 2 + half;

    float hid[2], bhv[2], bzv[2], brv[2], F0[2], G0[2], F1[2], G1[2];
    #pragma unroll
    for (int i = 0; i < 2; i++) {
        const int j = lt + 128 * i;
        hid[i] = hidden[b * NB + j];
        bhv[i] = bh[j]; bzv[i] = bz[j]; brv[i] = br[j];
        F0[i] = s_scale[0][j] * g_w[0][b * NB + j];
        G0[i] = s_scale[1][j] * g_w[1][b * NB + j];
        F1[i] = s_scale[2][j] * g_w[2][b * NB + j];
        G1[i] = s_scale[3][j] * g_w[3][b * NB + j];
    }

    // ---- round 1: 15 sums ----
    float v[15];
    #pragma unroll
    for (int k = 0; k < 15; k++) v[k] = 0.0f;
    #pragma unroll
    for (int i = 0; i < 2; i++) {
        v[0]  = fmaf(F0[i], F0[i], v[0]);   v[1]  = fmaf(G0[i], G0[i], v[1]);
        v[2]  = fmaf(F0[i], G0[i], v[2]);   v[3]  = fmaf(F0[i], bzv[i], v[3]);
        v[4]  = fmaf(G0[i], bzv[i], v[4]);  v[5]  = fmaf(bzv[i], bzv[i], v[5]);
        v[6]  = fmaf(F1[i], F1[i], v[6]);   v[7]  = fmaf(G1[i], G1[i], v[7]);
        v[8]  = fmaf(F1[i], G1[i], v[8]);   v[9]  = fmaf(F1[i], brv[i], v[9]);
        v[10] = fmaf(G1[i], brv[i], v[10]); v[11] = fmaf(brv[i], brv[i], v[11]);
        v[12] = fmaf(hid[i], hid[i], v[12]);v[13] = fmaf(bhv[i], bhv[i], v[13]);
        v[14] = fmaf(hid[i], bhv[i], v[14]);
    }
    #pragma unroll
    for (int k = 0; k < 15; k++) {
        #pragma unroll
        for (int o = 16; o; o >>= 1) v[k] += __shfl_xor_sync(0xffffffffu, v[k], o);
    }
    if (lane == 0) {
        #pragma unroll
        for (int k = 0; k < 15; k++) smr1[half][wih][k] = v[k];
    }
    __syncthreads();
    #pragma unroll
    for (int k = 0; k < 15; k++)
        v[k] = smr1[half][0][k] + smr1[half][1][k] + smr1[half][2][k] + smr1[half][3][k];

    const float sFF0 = v[0], sGG0 = v[1], sFG0 = v[2], sFb0 = v[3], sGb0 = v[4], sbb0 = v[5];
    const float sFF1 = v[6], sGG1 = v[7], sFG1 = v[8], sFb1 = v[9], sGb1 = v[10], sbb1 = v[11];
    const float shh = v[12], sbhbh = v[13], shbh = v[14];

    // ---- z gate ----
    MS z1 = madds(sFF0, sGG0, sFG0);
    float zcF = z1.m * z1.inv * z1.A, zcG = z1.m * z1.inv * z1.B;
    MS z2 = madds(z1.nc * z1.nc, sbb0, zcF * sFb0 + zcG * sGb0);
    float k2a = z2.m * z2.inv * z2.A, k2b = z2.m * z2.inv * z2.B;
    float facz = fatanh_(z2.nc) * frcp_(z2.nc);
    float zg[2];
    #pragma unroll
    for (int i = 0; i < 2; i++)
        zg[i] = fsigm_(facz * (k2a * (zcF * F0[i] + zcG * G0[i]) + k2b * bzv[i]));

    // ---- r gate ----
    MS r1 = madds(sFF1, sGG1, sFG1);
    float rcF = r1.m * r1.inv * r1.A, rcG = r1.m * r1.inv * r1.B;
    MS r2 = madds(r1.nc * r1.nc, sbb1, rcF * sFb1 + rcG * sGb1);
    float l2a = r2.m * r2.inv * r2.A, l2b = r2.m * r2.inv * r2.B;
    float facr = fatanh_(r2.nc) * frcp_(r2.nc);
    float rg[2];
    #pragma unroll
    for (int i = 0; i < 2; i++)
        rg[i] = fsigm_(facr * (l2a * (rcF * F1[i] + rcG * G1[i]) + l2b * brv[i]));

    // ---- round 2: 4 sums ----
    float v2[4] = {0.f, 0.f, 0.f, 0.f};
    #pragma unroll
    for (int i = 0; i < 2; i++) {
        v2[0] = fmaf(rg[i], rg[i], v2[0]);  v2[1] = fmaf(rg[i], bhv[i], v2[1]);
        v2[2] = fmaf(hid[i], rg[i], v2[2]); v2[3] = fmaf(zg[i], zg[i], v2[3]);
    }
    #pragma unroll
    for (int k = 0; k < 4; k++) {
        #pragma unroll
        for (int o = 16; o; o >>= 1) v2[k] += __shfl_xor_sync(0xffffffffu, v2[k], o);
    }
    if (lane == 0) {
        #pragma unroll
        for (int k = 0; k < 4; k++) smr2[half][wih][k] = v2[k];
    }
    __syncthreads();
    #pragma unroll
    for (int k = 0; k < 4; k++)
        v2[k] = smr2[half][0][k] + smr2[half][1][k] + smr2[half][2][k] + smr2[half][3][k];
    const float srr = v2[0], srbh = v2[1], shr = v2[2], szz = v2[3];

    // ---- h_tilde = madd(rg, bh); mh = madd(-hid, ht) ----
    MS h3 = madds(srr, sbhbh, srbh);
    float hA = h3.m * h3.inv * h3.A, hB = h3.m * h3.inv * h3.B;
    float sht_h = hA * shr + hB * shbh;
    MS h4 = madds(shh, h3.nc * h3.nc, -sht_h);
    float mA = -h4.m * h4.inv * h4.A;
    float mR =  h4.m * h4.inv * h4.B * hA;
    float mB =  h4.m * h4.inv * h4.B * hB;

    // ---- round 3: 2 sums ----
    float wx[2];
    float v3[2] = {0.f, 0.f};
    #pragma unroll
    for (int i = 0; i < 2; i++) {
        wx[i] = (mA * hid[i] + mR * rg[i] + mB * bhv[i]) * zg[i];
        v3[0] = fmaf(wx[i], wx[i], v3[0]);
        v3[1] = fmaf(hid[i], wx[i], v3[1]);
    }
    #pragma unroll
    for (int k = 0; k < 2; k++) {
        #pragma unroll
        for (int o = 16; o; o >>= 1) v3[k] += __shfl_xor_sync(0xffffffffu, v3[k], o);
    }
    if (lane == 0) {
        #pragma unroll
        for (int k = 0; k < 2; k++) smr3[half][wih][k] = v3[k];
    }
    __syncthreads();
    const float swx  = smr3[half][0][0] + smr3[half][1][0] + smr3[half][2][0] + smr3[half][3][0];
    const float shwx = smr3[half][0][1] + smr3[half][1][1] + smr3[half][2][1] + smr3[half][3][1];

    // ---- mobius pointwise mul + final add ----
    float xn  = fmaxf(fsqrt_(szz), EPSN);
    float wxn = fmaxf(fsqrt_(swx), EPSN);
    float tt  = fatanh_(fminf(xn, CLIPV));
    float f   = ftanh_(wxn * frcp_(xn) * tt);
    float pn  = fmaxf(f, EPSN);
    float cf  = f * frcp_(wxn);
    if (pn > MAXN) cf *= MAXN * frcp_(pn);
    float pnc = fminf(pn, MAXN);

    MS o5 = madds(shh, pnc * pnc, cf * shwx);
    float oH = o5.m * o5.inv * o5.A, oP = o5.m * o5.inv * o5.B * cf;

    #pragma unroll
    for (int i = 0; i < 2; i++)
        out[b * NB + lt + 128 * i] = oH * hid[i] + oP * wx[i];
}

// ---------------- launch ------------------------------------------------------
extern "C" void kernel_launch(void* const* d_in, const int* in_sizes, int n_in,
                              void* d_out, int out_size)
{
    const float* hyp_x  = (const float*)d_in[0];
    const float* hidden = (const float*)d_in[1];
    const float* Wz_z   = (const float*)d_in[2];
    const float* Wz_r   = (const float*)d_in[3];
    const float* Uz_z   = (const float*)d_in[4];
    const float* Uz_r   = (const float*)d_in[5];
    const float* Wr_z   = (const float*)d_in[6];
    const float* Wr_r   = (const float*)d_in[7];
    const float* Ur_z   = (const float*)d_in[8];
    const float* Ur_r   = (const float*)d_in[9];
    const float* b_z    = (const float*)d_in[14];
    const float* b_r    = (const float*)d_in[15];
    const float* b_h    = (const float*)d_in[16];
    float* out = (float*)d_out;

    fused_cell<<<NBLOCKS, 256>>>(hidden, hyp_x, Wz_z, Wz_r, Uz_z, Uz_r,
                                 Wr_z, Wr_r, Ur_z, Ur_r, b_z, b_r, b_h, out);
}